// round 12
// baseline (speedup 1.0000x reference)
#include <cuda_runtime.h>
#include <cuda_fp16.h>
#include <cstdint>
#include <cstddef>

// ---------------------------------------------------------------------------
// FuseLayer: out_i = sum_j relu(adj_i @ (x_ij @ W_ij) + b_ij)
// N = {8000, 4000, 2000}, DIM=128, row offsets {0, 8000, 12000}.
// Pipeline (portable sm_80-class ISA — ptxas targets sm_103 non-'a'):
//   zero X -> build X (gather/scatter)
//   Y = X @ W  (legacy tf32 mma), stored fp16 row-major [row][384]
//   ZR = relu((adj @ Y)*2^-10 + b): 128x128 tile, 256 thr, 2 CTAs/SM,
//        A f32 via LDG register prefetch -> in-reg fp16 convert -> STS to Ah
//        (no smem f32 round-trip), fp16 m16n8k16 mma + ldmatrix
//   out = fold3(ZR)
// ---------------------------------------------------------------------------

#define TOTROWS 14000

__device__ float  g_X [TOTROWS * 384];
__device__ float  g_ZR[TOTROWS * 384];
__device__ __half g_Yh[TOTROWS * 384];

// ------------------------------- helpers -----------------------------------

__device__ __forceinline__ uint32_t cvt_tf32(float f) {
    uint32_t r;
    asm("cvt.rna.tf32.f32 %0, %1;" : "=r"(r) : "f"(f));
    return r;
}
__device__ __forceinline__ uint32_t smem_u32(const void* p) {
    return (uint32_t)__cvta_generic_to_shared(p);
}
__device__ __forceinline__ void cp_async16(uint32_t dst, const void* src) {
    asm volatile("cp.async.cg.shared.global [%0], [%1], 16;\n" :: "r"(dst), "l"(src));
}
__device__ __forceinline__ void cp_async16_pred(uint32_t dst, const void* src, bool full) {
    int sz = full ? 16 : 0;
    asm volatile("cp.async.cg.shared.global [%0], [%1], 16, %2;\n"
                 :: "r"(dst), "l"(src), "r"(sz));
}
__device__ __forceinline__ void cp_commit() {
    asm volatile("cp.async.commit_group;\n");
}
template<int N>
__device__ __forceinline__ void cp_wait() {
    asm volatile("cp.async.wait_group %0;\n" :: "n"(N));
}
__device__ __forceinline__ void ldm_x4(uint32_t* r, uint32_t addr) {
    asm volatile("ldmatrix.sync.aligned.m8n8.x4.shared.b16 {%0,%1,%2,%3}, [%4];"
                 : "=r"(r[0]), "=r"(r[1]), "=r"(r[2]), "=r"(r[3]) : "r"(addr));
}
__device__ __forceinline__ void ldm_x4_t(uint32_t* r, uint32_t addr) {
    asm volatile("ldmatrix.sync.aligned.m8n8.x4.trans.shared.b16 {%0,%1,%2,%3}, [%4];"
                 : "=r"(r[0]), "=r"(r[1]), "=r"(r[2]), "=r"(r[3]) : "r"(addr));
}
__device__ __forceinline__ void mma_fp16(float* c, const uint32_t* a, const uint32_t* b) {
    asm volatile(
        "mma.sync.aligned.m16n8k16.row.col.f32.f16.f16.f32 "
        "{%0,%1,%2,%3}, {%4,%5,%6,%7}, {%8,%9}, {%0,%1,%2,%3};\n"
        : "+f"(c[0]), "+f"(c[1]), "+f"(c[2]), "+f"(c[3])
        : "r"(a[0]), "r"(a[1]), "r"(a[2]), "r"(a[3]), "r"(b[0]), "r"(b[1]));
}
__device__ __forceinline__ void mma_tf32(float* c, const uint32_t* a, const uint32_t* b) {
    asm volatile(
        "mma.sync.aligned.m16n8k8.row.col.f32.tf32.tf32.f32 "
        "{%0,%1,%2,%3}, {%4,%5,%6,%7}, {%8,%9}, {%0,%1,%2,%3};\n"
        : "+f"(c[0]), "+f"(c[1]), "+f"(c[2]), "+f"(c[3])
        : "r"(a[0]), "r"(a[1]), "r"(a[2]), "r"(a[3]), "r"(b[0]), "r"(b[1]));
}

__device__ __forceinline__ int levelM(int level)   { return level == 0 ? 8000 : (level == 1 ? 4000 : 2000); }
__device__ __forceinline__ int levelOff(int level) { return level == 0 ? 0    : (level == 1 ? 8000 : 12000); }

// ------------------------- X build (gather/scatter) ------------------------

__global__ void zero_x_kernel() {
    size_t i = (size_t)blockIdx.x * 1024 + threadIdx.x;   // 5250*1024 == 14000*384
    g_X[i] = 0.f;
}

__global__ void build_x_kernel(const float* __restrict__ h0,
                               const float* __restrict__ h1,
                               const float* __restrict__ h2,
                               const int* __restrict__ idx0,
                               const int* __restrict__ idx1) {
    int b = blockIdx.x, d = threadIdx.x;
    float v; size_t dst;
    if (b < 8000)       {                      v = h0[(size_t)b * 128 + d];                 dst = (size_t)b * 384 + d; }
    else if (b < 12000) { int r = b - 8000;    v = h1[(size_t)r * 128 + d];                 dst = (size_t)idx0[r] * 384 + 128 + d; }
    else if (b < 14000) { int r = b - 12000;   v = h2[(size_t)r * 128 + d];                 dst = (size_t)idx0[idx1[r]] * 384 + 256 + d; }
    else if (b < 18000) { int r = b - 14000;   v = h0[(size_t)idx0[r] * 128 + d];           dst = (size_t)(8000 + r) * 384 + d; }
    else if (b < 22000) { int r = b - 18000;   v = h1[(size_t)r * 128 + d];                 dst = (size_t)(8000 + r) * 384 + 128 + d; }
    else if (b < 24000) { int r = b - 22000;   v = h2[(size_t)r * 128 + d];                 dst = (size_t)(8000 + idx1[r]) * 384 + 256 + d; }
    else if (b < 26000) { int r = b - 24000;   v = h0[(size_t)idx0[idx1[r]] * 128 + d];     dst = (size_t)(12000 + r) * 384 + d; }
    else if (b < 28000) { int r = b - 26000;   v = h1[(size_t)idx1[r] * 128 + d];           dst = (size_t)(12000 + r) * 384 + 128 + d; }
    else                { int r = b - 28000;   v = h2[(size_t)r * 128 + d];                 dst = (size_t)(12000 + r) * 384 + 256 + d; }
    g_X[dst] = v;
}

// ---------------- tf32 GEMM: Yh = fp16(X @ W), row-major -------------------

#define XW_BM 128
#define XW_BK 16
#define XW_PADA 20
#define XW_PADB 132

struct XwSmem {
    float As[2][XW_BM * XW_PADA];
    float Bs[2][XW_BK * XW_PADB];
};

__global__ __launch_bounds__(256, 2)
void gemm_xw_kernel(const float* __restrict__ Ws) {
    const int level = blockIdx.z, j = blockIdx.y;
    const int M = levelM(level);
    if ((int)blockIdx.x * XW_BM >= M) return;
    const int ro = levelOff(level);
    const float* A = g_X + (size_t)ro * 384 + j * 128;          // lda=384
    const float* B = Ws + (size_t)(level * 3 + j) * 128 * 128;  // ldb=128

    __shared__ XwSmem sm;
    const int tid  = threadIdx.x;
    const int lane = tid & 31, wid = tid >> 5;
    const int warpM = wid >> 2, warpN = wid & 3;
    const int g = lane >> 2, tg = lane & 3;
    const int m0 = blockIdx.x * XW_BM;

    float acc[4][4][4];
    #pragma unroll
    for (int a = 0; a < 4; ++a)
        #pragma unroll
        for (int b = 0; b < 4; ++b)
            #pragma unroll
            for (int c = 0; c < 4; ++c) acc[a][b][c] = 0.f;

    auto loadStage = [&](int kt, int s) {
        const int kbase = kt * XW_BK;
        #pragma unroll
        for (int t = 0; t < 2; ++t) {
            int c  = tid + t * 256;
            int ar = c >> 2, aq = c & 3;
            int arow = m0 + ar;
            if (arow >= M) arow = M - 1;
            cp_async16(smem_u32(&sm.As[s][ar * XW_PADA + aq * 4]),
                       A + (size_t)arow * 384 + kbase + aq * 4);
        }
        #pragma unroll
        for (int t = 0; t < 2; ++t) {
            int c  = tid + t * 256;
            int br = c >> 5, bc = (c & 31) * 4;
            cp_async16(smem_u32(&sm.Bs[s][br * XW_PADB + bc]),
                       B + (size_t)(kbase + br) * 128 + bc);
        }
    };

    loadStage(0, 0);
    cp_commit();

    for (int kt = 0; kt < 8; ++kt) {   // K=128
        cp_wait<0>();
        __syncthreads();
        if (kt + 1 < 8) loadStage(kt + 1, (kt + 1) & 1);
        cp_commit();

        const int s = kt & 1;
        const float* As = sm.As[s];
        const float* Bs = sm.Bs[s];
        #pragma unroll
        for (int kk = 0; kk < XW_BK; kk += 8) {
            uint32_t afr[4][4], bfr[4][2];
            #pragma unroll
            for (int mf = 0; mf < 4; ++mf) {
                int r0 = warpM * 64 + mf * 16 + g;
                afr[mf][0] = cvt_tf32(As[(r0    ) * XW_PADA + kk + tg    ]);
                afr[mf][1] = cvt_tf32(As[(r0 + 8) * XW_PADA + kk + tg    ]);
                afr[mf][2] = cvt_tf32(As[(r0    ) * XW_PADA + kk + tg + 4]);
                afr[mf][3] = cvt_tf32(As[(r0 + 8) * XW_PADA + kk + tg + 4]);
            }
            #pragma unroll
            for (int nf = 0; nf < 4; ++nf) {
                int c0 = warpN * 32 + nf * 8 + g;
                bfr[nf][0] = cvt_tf32(Bs[(kk + tg    ) * XW_PADB + c0]);
                bfr[nf][1] = cvt_tf32(Bs[(kk + tg + 4) * XW_PADB + c0]);
            }
            #pragma unroll
            for (int mf = 0; mf < 4; ++mf)
                #pragma unroll
                for (int nf = 0; nf < 4; ++nf)
                    mma_tf32(acc[mf][nf], afr[mf], bfr[nf]);
        }
        __syncthreads();
    }

    // store fp16 row-major into Yh[:, j*128 + ...]
    #pragma unroll
    for (int mf = 0; mf < 4; ++mf) {
        int rbase = m0 + warpM * 64 + mf * 16 + g;
        #pragma unroll
        for (int nf = 0; nf < 4; ++nf) {
            int cbase = warpN * 32 + nf * 8 + tg * 2;
            #pragma unroll
            for (int rr = 0; rr < 2; ++rr) {
                int row = rbase + rr * 8;
                if (row < M) {
                    __half2 hv = __floats2half2_rn(acc[mf][nf][rr * 2],
                                                   acc[mf][nf][rr * 2 + 1]);
                    *reinterpret_cast<__half2*>(
                        &g_Yh[(size_t)(ro + row) * 384 + j * 128 + cbase]) = hv;
                }
            }
        }
    }
}

// ------- adj GEMM: ZR = relu(adj@Y * 2^-10 + b), LDG-prefetch A -----------
// CTA 128x128 tile, 256 threads = 8 warps (2 warpM x 4 warpN), warp 64x32.
// A: per-chunk LDG f32 register prefetch (one chunk ahead) -> in-register
// fp16 convert (x1024) -> STS into Ah (stride-80 ldmatrix layout). No A
// smem f32 round-trip. B: cp.async fp16 slots (4, 3 groups in flight).
// 2 CTAs/SM (45KB smem, ~120 regs).

#define BH_STRIDE 272                        // 128 halfs + 16B pad
#define BH_SLOT   (32 * BH_STRIDE)           // 8704
#define NSLOT     4
#define AH_STRIDE 80
#define AH_BYTES  (128 * AH_STRIDE)          // 10240
#define ADJ_SMEM  (NSLOT * BH_SLOT + AH_BYTES)   // 45056 -> 2 CTAs/SM

__global__ __launch_bounds__(256, 2)
void adj_fp16_kernel(const float* __restrict__ adj0,
                     const float* __restrict__ adj1,
                     const float* __restrict__ adj2,
                     const float* __restrict__ bs) {
    const int j = blockIdx.x, mt = blockIdx.y, level = blockIdx.z;
    const int Mlev = levelM(level), ro = levelOff(level);
    if (mt * 128 >= Mlev) return;
    const int m0 = mt * 128;
    const float*  A = (level == 0) ? adj0 : (level == 1) ? adj1 : adj2;
    const __half* B = g_Yh + (size_t)ro * 384 + j * 128;
    const int KT = (Mlev + 31) >> 5;   // 250 / 125 / 63

    extern __shared__ char dsm[];
    char* slots = dsm;                        // B fp16 slots
    char* AhPtr = dsm + NSLOT * BH_SLOT;      // fp16 A tile (single buffer)

    const int tid = threadIdx.x, lane = tid & 31, wid = tid >> 5;
    const int warpM = wid >> 2, warpN = wid & 3;   // 2 x 4

    float acc[4][4][4];
    #pragma unroll
    for (int a = 0; a < 4; ++a)
        #pragma unroll
        for (int b = 0; b < 4; ++b)
            #pragma unroll
            for (int c = 0; c < 4; ++c) acc[a][b][c] = 0.f;

    // --- A register-prefetch state: 16 f32/thread = row (tid>>1), 16 cols ---
    const int arow = tid >> 1;                // 0..127
    const int acol = (tid & 1) * 16;          // 0 or 16 within the 32-K chunk
    int gmr = m0 + arow; if (gmr >= Mlev) gmr = 0;   // clamp: rows >= Mlev unused
    const float* Arow = A + (size_t)gmr * Mlev;

    float4 pf[4];
    auto prefetchA = [&](int chunk) {
        const int k0 = chunk * 32 + acol;
        #pragma unroll
        for (int q = 0; q < 4; ++q) {
            int gk = k0 + q * 4;
            if (gk < Mlev)   // Mlev % 4 == 0, so float4 fully in-bounds
                pf[q] = *reinterpret_cast<const float4*>(Arow + gk);
            else
                pf[q] = make_float4(0.f, 0.f, 0.f, 0.f);
        }
    };

    const float CS = 1024.f;   // exact power of two, undone in epilogue
    auto storeA = [&]() {      // convert in regs, STS into Ah ldmatrix layout
        #pragma unroll
        for (int q = 0; q < 4; ++q) {
            __half2 h0 = __floats2half2_rn(pf[q].x * CS, pf[q].y * CS);
            __half2 h1 = __floats2half2_rn(pf[q].z * CS, pf[q].w * CS);
            uint2 o;
            o.x = *reinterpret_cast<uint32_t*>(&h0);
            o.y = *reinterpret_cast<uint32_t*>(&h1);
            *reinterpret_cast<uint2*>(
                AhPtr + arow * AH_STRIDE + (acol + q * 4) * 2) = o;
        }
    };

    auto load_stage = [&](int chunk, int slot) {   // B only
        const int k0 = chunk * 32;
        char* base = slots + slot * BH_SLOT;
        #pragma unroll
        for (int t = 0; t < 2; ++t) {
            int c = tid + t * 256;
            int r = c >> 4, ci = c & 15;
            int gk = k0 + r;
            bool ok = gk < Mlev;
            const __half* src = ok ? (B + (size_t)gk * 384 + ci * 8) : B;
            cp_async16_pred(smem_u32(base + r * BH_STRIDE + ci * 16), src, ok);
        }
        cp_commit();
    };

    // prologue
    prefetchA(0);
    load_stage(0, 0);
    load_stage(1, 1);
    load_stage(2, 2);

    const uint32_t ahB = smem_u32(AhPtr);
    const int rowA = warpM * 64 + (lane & 15);
    const int hi   = lane >> 4;
    const int rowB = lane & 15;

    for (int i = 0; i < KT; ++i) {
        const int slot = i & 3;
        cp_wait<2>();
        __syncthreads();           // prior chunk's Ah reads done; B slot ready

        storeA();                  // Ah <- chunk i (from prefetched regs)
        if (i + 1 < KT) prefetchA(i + 1);   // LDG in flight during mma below
        if (i + 3 < KT) load_stage(i + 3, (i + 3) & 3);
        else            cp_commit();        // keep group bookkeeping uniform
        __syncthreads();           // Ah visible to all warps

        const uint32_t bB = smem_u32(slots + slot * BH_SLOT);
        #pragma unroll
        for (int kk = 0; kk < 32; kk += 16) {
            uint32_t afr[4][4], bfr[2][4];
            #pragma unroll
            for (int mf = 0; mf < 4; ++mf)
                ldm_x4(afr[mf], ahB + (rowA + mf * 16) * AH_STRIDE
                                    + ((kk >> 3) + hi) * 16);
            #pragma unroll
            for (int nb = 0; nb < 2; ++nb) {
                int col = warpN * 32 + nb * 16 + hi * 8;
                ldm_x4_t(bfr[nb], bB + (kk + rowB) * BH_STRIDE + col * 2);
            }
            #pragma unroll
            for (int mf = 0; mf < 4; ++mf)
                #pragma unroll
                for (int nb = 0; nb < 2; ++nb) {
                    mma_fp16(acc[mf][nb * 2    ], afr[mf], &bfr[nb][0]);
                    mma_fp16(acc[mf][nb * 2 + 1], afr[mf], &bfr[nb][2]);
                }
        }
    }

    // epilogue: undo 2^10 adj scale, add bias, relu, store to ZR
    const float S = 1.f / 1024.f;
    const float* biasp = bs + (size_t)(level * 3 + j) * 128;
    const int rbase = m0 + warpM * 64 + (lane >> 2);
    #pragma unroll
    for (int nf = 0; nf < 4; ++nf) {
        int c0 = warpN * 32 + nf * 8 + (lane & 3) * 2;
        float b0 = __ldg(biasp + c0), b1 = __ldg(biasp + c0 + 1);
        #pragma unroll
        for (int mf = 0; mf < 4; ++mf) {
            int r0 = rbase + mf * 16;
            if (r0 < Mlev) {
                float2 v = make_float2(fmaxf(acc[mf][nf][0] * S + b0, 0.f),
                                       fmaxf(acc[mf][nf][1] * S + b1, 0.f));
                *reinterpret_cast<float2*>(
                    &g_ZR[(size_t)(ro + r0) * 384 + j * 128 + c0]) = v;
            }
            int r1 = r0 + 8;
            if (r1 < Mlev) {
                float2 v = make_float2(fmaxf(acc[mf][nf][2] * S + b0, 0.f),
                                       fmaxf(acc[mf][nf][3] * S + b1, 0.f));
                *reinterpret_cast<float2*>(
                    &g_ZR[(size_t)(ro + r1) * 384 + j * 128 + c0]) = v;
            }
        }
    }
}

// out[r,d] = ZR[r,d] + ZR[r,128+d] + ZR[r,256+d]
__global__ void reduce_kernel(float* __restrict__ out) {
    int r = blockIdx.x, d = threadIdx.x;
    const float* z = g_ZR + (size_t)r * 384;
    out[(size_t)r * 128 + d] = z[d] + z[128 + d] + z[256 + d];
}

// ------------------------------- launch ------------------------------------

extern "C" void kernel_launch(void* const* d_in, const int* in_sizes, int n_in,
                              void* d_out, int out_size) {
    const float* adj0 = (const float*)d_in[0];
    const float* adj1 = (const float*)d_in[1];
    const float* adj2 = (const float*)d_in[2];
    const float* h0   = (const float*)d_in[3];
    const float* h1   = (const float*)d_in[4];
    const float* h2   = (const float*)d_in[5];
    const int*   idx0 = (const int*)  d_in[6];
    const int*   idx1 = (const int*)  d_in[7];
    const float* Ws   = (const float*)d_in[8];
    const float* bs   = (const float*)d_in[9];
    float* out = (float*)d_out;

    // Unconditional (no static guards): idempotent, enqueues nothing.
    cudaFuncSetAttribute(adj_fp16_kernel,
                         cudaFuncAttributeMaxDynamicSharedMemorySize, ADJ_SMEM);

    zero_x_kernel <<<5250, 1024>>>();
    build_x_kernel<<<30000, 128>>>(h0, h1, h2, idx0, idx1);
    gemm_xw_kernel<<<dim3(63, 3, 3), 256>>>(Ws);
    adj_fp16_kernel<<<dim3(3, 63, 3), 256, ADJ_SMEM>>>(adj0, adj1, adj2, bs);
    reduce_kernel <<<14000, 128>>>(out);
    (void)in_sizes; (void)n_in; (void)out_size;
}

// round 14
// speedup vs baseline: 1.2998x; 1.2998x over previous
#include <cuda_runtime.h>
#include <cuda_fp16.h>
#include <cstdint>
#include <cstddef>

// ---------------------------------------------------------------------------
// FuseLayer: out_i = sum_j relu(adj_i @ (x_ij @ W_ij) + b_ij)
// N = {8000, 4000, 2000}, DIM=128, row offsets {0, 8000, 12000}.
// Pipeline (portable sm_80-class ISA — ptxas targets sm_103 non-'a'):
//   zero X -> build X (gather/scatter)
//   Y = X @ W  (legacy tf32 mma), stored fp16 row-major [row][384]
//   ZR = relu((adj @ Y)*2^-10 + b): 128x128 tile, 256 thr, 2 CTAs/SM,
//        A f32 via cp.async + per-chunk in-smem fp16 convert (x1024) into a
//        packed XOR-swizzled Ah (conflict-free STS.128 + ldmatrix),
//        fp16 m16n8k16 mma + ldmatrix
//   out = fold3(ZR)
// ---------------------------------------------------------------------------

#define TOTROWS 14000

__device__ float  g_X [TOTROWS * 384];
__device__ float  g_ZR[TOTROWS * 384];
__device__ __half g_Yh[TOTROWS * 384];

// ------------------------------- helpers -----------------------------------

__device__ __forceinline__ uint32_t cvt_tf32(float f) {
    uint32_t r;
    asm("cvt.rna.tf32.f32 %0, %1;" : "=r"(r) : "f"(f));
    return r;
}
__device__ __forceinline__ uint32_t smem_u32(const void* p) {
    return (uint32_t)__cvta_generic_to_shared(p);
}
__device__ __forceinline__ void cp_async16(uint32_t dst, const void* src) {
    asm volatile("cp.async.cg.shared.global [%0], [%1], 16;\n" :: "r"(dst), "l"(src));
}
__device__ __forceinline__ void cp_async16_pred(uint32_t dst, const void* src, bool full) {
    int sz = full ? 16 : 0;
    asm volatile("cp.async.cg.shared.global [%0], [%1], 16, %2;\n"
                 :: "r"(dst), "l"(src), "r"(sz));
}
__device__ __forceinline__ void cp_commit() {
    asm volatile("cp.async.commit_group;\n");
}
template<int N>
__device__ __forceinline__ void cp_wait() {
    asm volatile("cp.async.wait_group %0;\n" :: "n"(N));
}
__device__ __forceinline__ void ldm_x4(uint32_t* r, uint32_t addr) {
    asm volatile("ldmatrix.sync.aligned.m8n8.x4.shared.b16 {%0,%1,%2,%3}, [%4];"
                 : "=r"(r[0]), "=r"(r[1]), "=r"(r[2]), "=r"(r[3]) : "r"(addr));
}
__device__ __forceinline__ void ldm_x4_t(uint32_t* r, uint32_t addr) {
    asm volatile("ldmatrix.sync.aligned.m8n8.x4.trans.shared.b16 {%0,%1,%2,%3}, [%4];"
                 : "=r"(r[0]), "=r"(r[1]), "=r"(r[2]), "=r"(r[3]) : "r"(addr));
}
__device__ __forceinline__ void mma_fp16(float* c, const uint32_t* a, const uint32_t* b) {
    asm volatile(
        "mma.sync.aligned.m16n8k16.row.col.f32.f16.f16.f32 "
        "{%0,%1,%2,%3}, {%4,%5,%6,%7}, {%8,%9}, {%0,%1,%2,%3};\n"
        : "+f"(c[0]), "+f"(c[1]), "+f"(c[2]), "+f"(c[3])
        : "r"(a[0]), "r"(a[1]), "r"(a[2]), "r"(a[3]), "r"(b[0]), "r"(b[1]));
}
__device__ __forceinline__ void mma_tf32(float* c, const uint32_t* a, const uint32_t* b) {
    asm volatile(
        "mma.sync.aligned.m16n8k8.row.col.f32.tf32.tf32.f32 "
        "{%0,%1,%2,%3}, {%4,%5,%6,%7}, {%8,%9}, {%0,%1,%2,%3};\n"
        : "+f"(c[0]), "+f"(c[1]), "+f"(c[2]), "+f"(c[3])
        : "r"(a[0]), "r"(a[1]), "r"(a[2]), "r"(a[3]), "r"(b[0]), "r"(b[1]));
}

__device__ __forceinline__ int levelM(int level)   { return level == 0 ? 8000 : (level == 1 ? 4000 : 2000); }
__device__ __forceinline__ int levelOff(int level) { return level == 0 ? 0    : (level == 1 ? 8000 : 12000); }

// ------------------------- X build (gather/scatter) ------------------------

__global__ void zero_x_kernel() {
    size_t i = (size_t)blockIdx.x * 1024 + threadIdx.x;   // 5250*1024 == 14000*384
    g_X[i] = 0.f;
}

__global__ void build_x_kernel(const float* __restrict__ h0,
                               const float* __restrict__ h1,
                               const float* __restrict__ h2,
                               const int* __restrict__ idx0,
                               const int* __restrict__ idx1) {
    int b = blockIdx.x, d = threadIdx.x;
    float v; size_t dst;
    if (b < 8000)       {                      v = h0[(size_t)b * 128 + d];                 dst = (size_t)b * 384 + d; }
    else if (b < 12000) { int r = b - 8000;    v = h1[(size_t)r * 128 + d];                 dst = (size_t)idx0[r] * 384 + 128 + d; }
    else if (b < 14000) { int r = b - 12000;   v = h2[(size_t)r * 128 + d];                 dst = (size_t)idx0[idx1[r]] * 384 + 256 + d; }
    else if (b < 18000) { int r = b - 14000;   v = h0[(size_t)idx0[r] * 128 + d];           dst = (size_t)(8000 + r) * 384 + d; }
    else if (b < 22000) { int r = b - 18000;   v = h1[(size_t)r * 128 + d];                 dst = (size_t)(8000 + r) * 384 + 128 + d; }
    else if (b < 24000) { int r = b - 22000;   v = h2[(size_t)r * 128 + d];                 dst = (size_t)(8000 + idx1[r]) * 384 + 256 + d; }
    else if (b < 26000) { int r = b - 24000;   v = h0[(size_t)idx0[idx1[r]] * 128 + d];     dst = (size_t)(12000 + r) * 384 + d; }
    else if (b < 28000) { int r = b - 26000;   v = h1[(size_t)idx1[r] * 128 + d];           dst = (size_t)(12000 + r) * 384 + 128 + d; }
    else                { int r = b - 28000;   v = h2[(size_t)r * 128 + d];                 dst = (size_t)(12000 + r) * 384 + 256 + d; }
    g_X[dst] = v;
}

// ---------------- tf32 GEMM: Yh = fp16(X @ W), row-major -------------------

#define XW_BM 128
#define XW_BK 16
#define XW_PADA 20
#define XW_PADB 132

struct XwSmem {
    float As[2][XW_BM * XW_PADA];
    float Bs[2][XW_BK * XW_PADB];
};

__global__ __launch_bounds__(256, 2)
void gemm_xw_kernel(const float* __restrict__ Ws) {
    const int level = blockIdx.z, j = blockIdx.y;
    const int M = levelM(level);
    if ((int)blockIdx.x * XW_BM >= M) return;
    const int ro = levelOff(level);
    const float* A = g_X + (size_t)ro * 384 + j * 128;          // lda=384
    const float* B = Ws + (size_t)(level * 3 + j) * 128 * 128;  // ldb=128

    __shared__ XwSmem sm;
    const int tid  = threadIdx.x;
    const int lane = tid & 31, wid = tid >> 5;
    const int warpM = wid >> 2, warpN = wid & 3;
    const int g = lane >> 2, tg = lane & 3;
    const int m0 = blockIdx.x * XW_BM;

    float acc[4][4][4];
    #pragma unroll
    for (int a = 0; a < 4; ++a)
        #pragma unroll
        for (int b = 0; b < 4; ++b)
            #pragma unroll
            for (int c = 0; c < 4; ++c) acc[a][b][c] = 0.f;

    auto loadStage = [&](int kt, int s) {
        const int kbase = kt * XW_BK;
        #pragma unroll
        for (int t = 0; t < 2; ++t) {
            int c  = tid + t * 256;
            int ar = c >> 2, aq = c & 3;
            int arow = m0 + ar;
            if (arow >= M) arow = M - 1;
            cp_async16(smem_u32(&sm.As[s][ar * XW_PADA + aq * 4]),
                       A + (size_t)arow * 384 + kbase + aq * 4);
        }
        #pragma unroll
        for (int t = 0; t < 2; ++t) {
            int c  = tid + t * 256;
            int br = c >> 5, bc = (c & 31) * 4;
            cp_async16(smem_u32(&sm.Bs[s][br * XW_PADB + bc]),
                       B + (size_t)(kbase + br) * 128 + bc);
        }
    };

    loadStage(0, 0);
    cp_commit();

    for (int kt = 0; kt < 8; ++kt) {   // K=128
        cp_wait<0>();
        __syncthreads();
        if (kt + 1 < 8) loadStage(kt + 1, (kt + 1) & 1);
        cp_commit();

        const int s = kt & 1;
        const float* As = sm.As[s];
        const float* Bs = sm.Bs[s];
        #pragma unroll
        for (int kk = 0; kk < XW_BK; kk += 8) {
            uint32_t afr[4][4], bfr[4][2];
            #pragma unroll
            for (int mf = 0; mf < 4; ++mf) {
                int r0 = warpM * 64 + mf * 16 + g;
                afr[mf][0] = cvt_tf32(As[(r0    ) * XW_PADA + kk + tg    ]);
                afr[mf][1] = cvt_tf32(As[(r0 + 8) * XW_PADA + kk + tg    ]);
                afr[mf][2] = cvt_tf32(As[(r0    ) * XW_PADA + kk + tg + 4]);
                afr[mf][3] = cvt_tf32(As[(r0 + 8) * XW_PADA + kk + tg + 4]);
            }
            #pragma unroll
            for (int nf = 0; nf < 4; ++nf) {
                int c0 = warpN * 32 + nf * 8 + g;
                bfr[nf][0] = cvt_tf32(Bs[(kk + tg    ) * XW_PADB + c0]);
                bfr[nf][1] = cvt_tf32(Bs[(kk + tg + 4) * XW_PADB + c0]);
            }
            #pragma unroll
            for (int mf = 0; mf < 4; ++mf)
                #pragma unroll
                for (int nf = 0; nf < 4; ++nf)
                    mma_tf32(acc[mf][nf], afr[mf], bfr[nf]);
        }
        __syncthreads();
    }

    // store fp16 row-major into Yh[:, j*128 + ...]
    #pragma unroll
    for (int mf = 0; mf < 4; ++mf) {
        int rbase = m0 + warpM * 64 + mf * 16 + g;
        #pragma unroll
        for (int nf = 0; nf < 4; ++nf) {
            int cbase = warpN * 32 + nf * 8 + tg * 2;
            #pragma unroll
            for (int rr = 0; rr < 2; ++rr) {
                int row = rbase + rr * 8;
                if (row < M) {
                    __half2 hv = __floats2half2_rn(acc[mf][nf][rr * 2],
                                                   acc[mf][nf][rr * 2 + 1]);
                    *reinterpret_cast<__half2*>(
                        &g_Yh[(size_t)(ro + row) * 384 + j * 128 + cbase]) = hv;
                }
            }
        }
    }
}

// ------- adj GEMM: ZR = relu(adj@Y * 2^-10 + b), in-smem A convert --------
// CTA 128x128 tile, 256 threads = 8 warps (2 warpM x 4 warpN), warp 64x32.
// A arrives f32 via cp.async (XOR-swizzled 128B rows); per chunk converted
// in-smem to fp16 x1024 into Ah: PACKED XOR layout — 2 logical 64B rows per
// 128B smem row, 16B chunk position = ((r&1)*4 + c16) ^ ((r>>1)&7).
// Conflict-free STS.128 convert and conflict-free ldmatrix (verified per
// 8-lane phase). 4 slots, 3 cp.async groups in flight. 2 CTAs/SM.

#define AF32_SLOT 16384                      // 128 rows x 128B, XOR-swizzled
#define BH_STRIDE 272                        // 128 halfs + 16B pad
#define BH_SLOT   (32 * BH_STRIDE)           // 8704
#define SLOT_BYTES (AF32_SLOT + BH_SLOT)     // 25088
#define NSLOT     4
#define AH_BYTES  8192                       // 64 smem rows x 128B (packed)
#define ADJ_SMEM  (NSLOT * SLOT_BYTES + AH_BYTES)   // 108544 -> 2 CTAs/SM

__global__ __launch_bounds__(256, 2)
void adj_fp16_kernel(const float* __restrict__ adj0,
                     const float* __restrict__ adj1,
                     const float* __restrict__ adj2,
                     const float* __restrict__ bs) {
    const int j = blockIdx.x, mt = blockIdx.y, level = blockIdx.z;
    const int Mlev = levelM(level), ro = levelOff(level);
    if (mt * 128 >= Mlev) return;
    const int m0 = mt * 128;
    const float*  A = (level == 0) ? adj0 : (level == 1) ? adj1 : adj2;
    const __half* B = g_Yh + (size_t)ro * 384 + j * 128;
    const int KT = (Mlev + 31) >> 5;   // 250 / 125 / 63

    extern __shared__ char dsm[];
    char* slots = dsm;
    char* AhPtr = dsm + NSLOT * SLOT_BYTES;

    const int tid = threadIdx.x, lane = tid & 31, wid = tid >> 5;
    const int warpM = wid >> 2, warpN = wid & 3;   // 2 x 4

    float acc[4][4][4];
    #pragma unroll
    for (int a = 0; a < 4; ++a)
        #pragma unroll
        for (int b = 0; b < 4; ++b)
            #pragma unroll
            for (int c = 0; c < 4; ++c) acc[a][b][c] = 0.f;

    auto load_stage = [&](int chunk, int slot) {
        const int k0 = chunk * 32;
        char* base = slots + slot * SLOT_BYTES;
        // A: 128 rows x 8 x 16B (f32), XOR swizzle on 16B column, 4/thread
        #pragma unroll
        for (int t = 0; t < 4; ++t) {
            int c = tid + t * 256;
            int r = c >> 3, ci = c & 7;
            int gm = m0 + r, gk = k0 + ci * 4;
            bool ok = (gm < Mlev) && (gk < Mlev);
            const float* src = ok ? (A + (size_t)gm * Mlev + gk) : A;
            cp_async16_pred(smem_u32(base + r * 128 + ((ci ^ (r & 7)) * 16)),
                            src, ok);
        }
        // B: 32 rows x 16 x 16B (fp16), 2/thread
        #pragma unroll
        for (int t = 0; t < 2; ++t) {
            int c = tid + t * 256;
            int r = c >> 4, ci = c & 15;
            int gk = k0 + r;
            bool ok = gk < Mlev;
            const __half* src = ok ? (B + (size_t)gk * 384 + ci * 8) : B;
            cp_async16_pred(smem_u32(base + AF32_SLOT + r * BH_STRIDE + ci * 16),
                            src, ok);
        }
        cp_commit();
    };

    // prologue: 3 groups in flight (KT >= 63 always)
    load_stage(0, 0);
    load_stage(1, 1);
    load_stage(2, 2);

    const uint32_t ahB = smem_u32(AhPtr);
    // ldmatrix A lane geometry (packed XOR Ah layout)
    const int rA   = warpM * 64 + (lane & 15);   // logical row base (+ mf*16)
    const int cHi  = lane >> 4;                  // 0/1: second 16B chunk
    const int sBase = rA >> 1;                   // smem row base (mf adds 8)
    const int swA   = sBase & 7;                 // XOR key (invariant in mf)
    const int odd4  = (rA & 1) * 4;              // odd logical row offset
    const int rowB = lane & 15;
    const int hi   = lane >> 4;
    const float CS = 1024.f;   // exact power of two, undone in epilogue

    for (int i = 0; i < KT; ++i) {
        const int slot = i & 3;
        cp_wait<2>();
        __syncthreads();
        if (i + 3 < KT) load_stage(i + 3, (i + 3) & 3);
        else            cp_commit();   // keep group bookkeeping uniform

        // convert A f32 -> fp16 (x1024) into packed-XOR Ah.
        // thread: logical row r = tid>>1, half h = tid&1 (cols 16h..16h+15)
        {
            const char* af = slots + slot * SLOT_BYTES;
            int r = tid >> 1, h = tid & 1;
            int s = r >> 1, sw = s & 7, o4 = (r & 1) * 4;
            float4 v[4];
            #pragma unroll
            for (int q = 0; q < 4; ++q) {
                int cq = h * 4 + q;
                v[q] = *reinterpret_cast<const float4*>(
                    af + r * 128 + ((cq ^ (r & 7)) * 16));
            }
            #pragma unroll
            for (int qq = 0; qq < 2; ++qq) {
                __half2 h0 = __floats2half2_rn(v[2*qq].x * CS, v[2*qq].y * CS);
                __half2 h1 = __floats2half2_rn(v[2*qq].z * CS, v[2*qq].w * CS);
                __half2 h2 = __floats2half2_rn(v[2*qq+1].x * CS, v[2*qq+1].y * CS);
                __half2 h3 = __floats2half2_rn(v[2*qq+1].z * CS, v[2*qq+1].w * CS);
                uint4 o;
                o.x = *reinterpret_cast<uint32_t*>(&h0);
                o.y = *reinterpret_cast<uint32_t*>(&h1);
                o.z = *reinterpret_cast<uint32_t*>(&h2);
                o.w = *reinterpret_cast<uint32_t*>(&h3);
                int c16 = 2 * h + qq;
                *reinterpret_cast<uint4*>(
                    AhPtr + s * 128 + (((o4 + c16) ^ sw) * 16)) = o;
            }
        }
        __syncthreads();

        const uint32_t bB = smem_u32(slots + slot * SLOT_BYTES + AF32_SLOT);
        #pragma unroll
        for (int kk = 0; kk < 32; kk += 16) {
            uint32_t afr[4][4], bfr[2][4];
            #pragma unroll
            for (int mf = 0; mf < 4; ++mf) {
                int c16 = (kk >> 3) + cHi;
                ldm_x4(afr[mf], ahB + (sBase + mf * 8) * 128
                                    + (((odd4 + c16) ^ swA) * 16));
            }
            #pragma unroll
            for (int nb = 0; nb < 2; ++nb) {
                int col = warpN * 32 + nb * 16 + hi * 8;
                ldm_x4_t(bfr[nb], bB + (kk + rowB) * BH_STRIDE + col * 2);
            }
            #pragma unroll
            for (int mf = 0; mf < 4; ++mf)
                #pragma unroll
                for (int nb = 0; nb < 2; ++nb) {
                    mma_fp16(acc[mf][nb * 2    ], afr[mf], &bfr[nb][0]);
                    mma_fp16(acc[mf][nb * 2 + 1], afr[mf], &bfr[nb][2]);
                }
        }
    }

    // epilogue: undo 2^10 adj scale, add bias, relu, store to ZR
    const float S = 1.f / 1024.f;
    const float* biasp = bs + (size_t)(level * 3 + j) * 128;
    const int rbase = m0 + warpM * 64 + (lane >> 2);
    #pragma unroll
    for (int nf = 0; nf < 4; ++nf) {
        int c0 = warpN * 32 + nf * 8 + (lane & 3) * 2;
        float b0 = __ldg(biasp + c0), b1 = __ldg(biasp + c0 + 1);
        #pragma unroll
        for (int mf = 0; mf < 4; ++mf) {
            int r0 = rbase + mf * 16;
            if (r0 < Mlev) {
                float2 v = make_float2(fmaxf(acc[mf][nf][0] * S + b0, 0.f),
                                       fmaxf(acc[mf][nf][1] * S + b1, 0.f));
                *reinterpret_cast<float2*>(
                    &g_ZR[(size_t)(ro + r0) * 384 + j * 128 + c0]) = v;
            }
            int r1 = r0 + 8;
            if (r1 < Mlev) {
                float2 v = make_float2(fmaxf(acc[mf][nf][2] * S + b0, 0.f),
                                       fmaxf(acc[mf][nf][3] * S + b1, 0.f));
                *reinterpret_cast<float2*>(
                    &g_ZR[(size_t)(ro + r1) * 384 + j * 128 + c0]) = v;
            }
        }
    }
}

// out[r,d] = ZR[r,d] + ZR[r,128+d] + ZR[r,256+d]
__global__ void reduce_kernel(float* __restrict__ out) {
    int r = blockIdx.x, d = threadIdx.x;
    const float* z = g_ZR + (size_t)r * 384;
    out[(size_t)r * 128 + d] = z[d] + z[128 + d] + z[256 + d];
}

// ------------------------------- launch ------------------------------------

extern "C" void kernel_launch(void* const* d_in, const int* in_sizes, int n_in,
                              void* d_out, int out_size) {
    const float* adj0 = (const float*)d_in[0];
    const float* adj1 = (const float*)d_in[1];
    const float* adj2 = (const float*)d_in[2];
    const float* h0   = (const float*)d_in[3];
    const float* h1   = (const float*)d_in[4];
    const float* h2   = (const float*)d_in[5];
    const int*   idx0 = (const int*)  d_in[6];
    const int*   idx1 = (const int*)  d_in[7];
    const float* Ws   = (const float*)d_in[8];
    const float* bs   = (const float*)d_in[9];
    float* out = (float*)d_out;

    // Unconditional (no static guards): idempotent, enqueues nothing.
    cudaFuncSetAttribute(adj_fp16_kernel,
                         cudaFuncAttributeMaxDynamicSharedMemorySize, ADJ_SMEM);

    zero_x_kernel <<<5250, 1024>>>();
    build_x_kernel<<<30000, 128>>>(h0, h1, h2, idx0, idx1);
    gemm_xw_kernel<<<dim3(63, 3, 3), 256>>>(Ws);
    adj_fp16_kernel<<<dim3(3, 63, 3), 256, ADJ_SMEM>>>(adj0, adj1, adj2, bs);
    reduce_kernel <<<14000, 128>>>(out);
    (void)in_sizes; (void)n_in; (void)out_size;
}